// round 16
// baseline (speedup 1.0000x reference)
#include <cuda_runtime.h>
#include <stdint.h>
#include <math.h>

#define BB 32
#define TT 256
#define INS 64
#define HH 128
#define G4 512
#define EPSV 1e-7f
#define NC 4              // CTAs per cluster (k-split quarters)

typedef unsigned long long u64;
typedef unsigned int u32;

// ---- static device scratch (no cudaMalloc allowed) ----
__device__ __align__(16) u64 g_whp[32 * 512 * 2];   // W_hh packed: [k4][row] -> float4 as 2x u64
__device__ float g_gx[BB * TT * G4];                // precomputed input gate contributions

__device__ __forceinline__ u64 ffma2(u64 a, u64 b, u64 c) {
    u64 d;
    asm("fma.rn.f32x2 %0, %1, %2, %3;" : "=l"(d) : "l"(a), "l"(b), "l"(c));
    return d;
}
__device__ __forceinline__ float f2sum(u64 v) {
    float2 f = *reinterpret_cast<float2*>(&v);
    return f.x + f.y;
}
// accuracy-safe nonlinearities (tanh.approx fails the attn_w check: R10)
__device__ __forceinline__ float fsig(float x)  { return 1.0f / (1.0f + __expf(-x)); }
__device__ __forceinline__ float ftanh(float x) { return 2.0f / (1.0f + __expf(-2.0f * x)) - 1.0f; }

__device__ __forceinline__ u32 smem_u32(const void* p) {
    u32 a;
    asm("{ .reg .u64 t; cvta.to.shared.u64 t, %1; cvt.u32.u64 %0, t; }" : "=r"(a) : "l"(p));
    return a;
}

__device__ __forceinline__ void mbar_wait(u32 mb, u32 parity) {
    asm volatile(
        "{\n\t"
        ".reg .pred P;\n\t"
        "WL_%=:\n\t"
        "mbarrier.try_wait.parity.acquire.cta.shared::cta.b64 P, [%0], %1, 0x989680;\n\t"
        "@P bra.uni WD_%=;\n\t"
        "bra.uni WL_%=;\n\t"
        "WD_%=:\n\t"
        "}"
        :: "r"(mb), "r"(parity) : "memory");
}
__device__ __forceinline__ void st_async_f32(u32 addr, float v, u32 mb) {
    asm volatile("st.async.shared::cluster.mbarrier::complete_tx::bytes.f32 [%0], %1, [%2];"
                 :: "r"(addr), "f"(v), "r"(mb) : "memory");
}

// ---------------- fused pack + gx kernel ----------------
__global__ __launch_bounds__(512) void gxpack_kernel(const float* __restrict__ x,
                                                     const float* __restrict__ W_ih,
                                                     const float* __restrict__ W_hh,
                                                     const float* __restrict__ b_ih,
                                                     const float* __restrict__ b_hh) {
    int b = blockIdx.x, ty = blockIdx.y, j = threadIdx.x;

    if (ty == 0) {
        float* whp = (float*)g_whp;
        for (int idx = b * 512 + j; idx < G4 * HH; idx += 32 * 512) {
            int r = idx >> 7, k = idx & 127;
            whp[((k >> 2) * 512 + r) * 4 + (k & 3)] = W_hh[idx];
        }
    }

    __shared__ float xs[16][INS];
    int t0 = ty * 16;
    for (int idx = j; idx < 16 * INS; idx += 512)
        xs[idx >> 6][idx & 63] = x[(b * TT + t0 + (idx >> 6)) * INS + (idx & 63)];

    float4 w[16];
    const float4* wr = (const float4*)(W_ih + j * INS);
#pragma unroll
    for (int k4 = 0; k4 < 16; k4++) w[k4] = wr[k4];
    float bs = b_ih[j] + b_hh[j];
    __syncthreads();

    for (int tt = 0; tt < 16; tt++) {
        float acc = bs;
#pragma unroll
        for (int k4 = 0; k4 < 16; k4++) {
            acc = fmaf(w[k4].x, xs[tt][4 * k4 + 0], acc);
            acc = fmaf(w[k4].y, xs[tt][4 * k4 + 1], acc);
            acc = fmaf(w[k4].z, xs[tt][4 * k4 + 2], acc);
            acc = fmaf(w[k4].w, xs[tt][4 * k4 + 3], acc);
        }
        g_gx[(b * TT + t0 + tt) * G4 + j] = acc;
    }
}

// ---------------- recurrent kernel: cluster of 4 CTAs per batch row ----------------
// CTA rank r handles k-quarter r (32 cols, 16 regs/thread). Partials broadcast
// all-to-all via st.async into gpart[p][gate][quarter] (transposed: tail reads one
// LDS.128 per gate). Tail + top-5 fully replicated per CTA. Warp 16 = scheduler
// (expect_tx + score sbn computed directly from h_sh + top-5).
__global__ __launch_bounds__(544) void rec_kernel(const float* __restrict__ w_t,
                                                  float* __restrict__ out) {
    int tid = threadIdx.x, lane = tid & 31, wrp = tid >> 5;
    int b = blockIdx.x >> 2;

    u32 rank;
    asm("mov.u32 %0, %%cluster_ctarank;" : "=r"(rank));

    __shared__ __align__(16) float h_sh[HH];
    __shared__ __align__(16) float gpart[2][G4][NC];   // [parity][gate][quarter] (16 KB)
    __shared__ __align__(16) float slots[5][HH];
    __shared__ float redA[4];
    __shared__ float sb_arr[8];
    __shared__ float top5v[5];
    __shared__ int   top5r[5], top5s[5], rowslot[5], evslot;
    __shared__ float wa_s[HH], wb_s[HH];
    __shared__ __align__(8) u64 mbar[2];

    float* out_c = out;             // [B,H]
    float* out_w = out + BB * HH;   // [B,T]
    const float* gxb = g_gx + (size_t)b * TT * G4;

    if (tid < HH) {
        h_sh[tid] = 0.0f;
        slots[0][tid] = 0.0f;
        wa_s[tid] = w_t[tid];
        wb_s[tid] = w_t[HH + tid];
    }
    if (tid == 0) {
        sb_arr[0] = 0.0f;
        top5v[0] = 0.0f; top5r[0] = 0; top5s[0] = 0;
        for (int q = 1; q < 5; q++) { top5v[q] = -1e30f; top5r[q] = -1; top5s[q] = q; }
        rowslot[0] = 0;
        evslot = -1;
        asm volatile("mbarrier.init.shared.b64 [%0], 1;" :: "r"(smem_u32(&mbar[0])) : "memory");
        asm volatile("mbarrier.init.shared.b64 [%0], 1;" :: "r"(smem_u32(&mbar[1])) : "memory");
    }
    if (rank == 0 && tid < TT) out_w[b * TT + tid] = 0.0f;

    // destination addresses in all 4 CTAs: &gpart[0][0][myrank] and mbar[0]
    u32 mbl = smem_u32(&mbar[0]);
    u32 gll = smem_u32(&gpart[0][0][rank]);
    u32 dg[NC], dm[NC];
#pragma unroll
    for (int r = 0; r < NC; r++) {
        asm("mapa.shared::cluster.u32 %0, %1, %2;" : "=r"(dg[r]) : "r"(gll), "r"((u32)r));
        asm("mapa.shared::cluster.u32 %0, %1, %2;" : "=r"(dm[r]) : "r"(mbl), "r"((u32)r));
    }

    float c_reg = 0.0f;
    float ac = 0.0f;
    u32 ph0 = 0, ph1 = 0;

    // this CTA's W_hh quarter: rows = gate (tid), cols = [rank*32, rank*32+32)
    ulonglong2 wc[8];
    float gxv = 0.0f;
    if (tid < 512) {
        const ulonglong2* wp = (const ulonglong2*)g_whp;
#pragma unroll
        for (int k4 = 0; k4 < 8; k4++) wc[k4] = wp[((int)rank * 8 + k4) * 512 + tid];
        if (rank == 0) gxv = gxb[tid];   // gx folded into rank-0 partial
    }

    __syncthreads();
    asm volatile("barrier.cluster.arrive.aligned;" ::: "memory");
    asm volatile("barrier.cluster.wait.aligned;"   ::: "memory");

    for (int i = 0; i < TT; i++) {
        int p = i & 1;
        u32 poff = (u32)p * (u32)(G4 * NC * 4);   // parity offset in gpart bytes
        u32 moff = (u32)p * 8u;

        if (tid < 512) {
            // ---- GEMV quarter (register weights); rank 0 adds gx ----
            const ulonglong2* h2 = (const ulonglong2*)h_sh;
            u64 a0 = 0ull, a1 = 0ull, a2 = 0ull, a3 = 0ull;
#pragma unroll
            for (int k4 = 0; k4 < 8; k4++) {
                ulonglong2 w = wc[k4];
                ulonglong2 hv = h2[(int)rank * 8 + k4];
                if (k4 & 1) { a2 = ffma2(w.x, hv.x, a2); a3 = ffma2(w.y, hv.y, a3); }
                else        { a0 = ffma2(w.x, hv.x, a0); a1 = ffma2(w.y, hv.y, a1); }
            }
            float part = gxv + (f2sum(a0) + f2sum(a1)) + (f2sum(a2) + f2sum(a3));
            if (rank == 0 && i + 1 < TT) gxv = gxb[(i + 1) * G4 + tid];  // prefetch

            // broadcast partial to all 4 CTAs: slot [gate=tid][quarter=rank]
            u32 toff = poff + (u32)tid * 16u;
#pragma unroll
            for (int r = 0; r < NC; r++)
                st_async_f32(dg[r] + toff, part, dm[r] + moff);

            if (tid < HH) {
                // overlap DSMEM RTT: sync with scheduler warp, insert evicted slot
                asm volatile("bar.sync 2, 160;" ::: "memory");
                int ev = evslot;
                if (ev >= 0) slots[ev][tid] = h_sh[tid];   // row i = h(i-1)

                // wait for all 8192 bytes of partials
                if (p) { mbar_wait(mbl + 8u, ph1); ph1 ^= 1u; }
                else   { mbar_wait(mbl,      ph0); ph0 ^= 1u; }

                // gates: one LDS.128 per gate row (quarters contiguous)
                const float4* gp = (const float4*)&gpart[p][0][0];
                float4 vi = gp[tid];
                float4 vf = gp[HH + tid];
                float4 vg = gp[2 * HH + tid];
                float4 vo = gp[3 * HH + tid];
                float gi = (vi.x + vi.y) + (vi.z + vi.w);
                float gf = (vf.x + vf.y) + (vf.z + vf.w);
                float gg = (vg.x + vg.y) + (vg.z + vg.w);
                float go = (vo.x + vo.y) + (vo.z + vo.w);
                float ti = fsig(gi), tf = fsig(gf), tg = ftanh(gg), to = fsig(go);
                c_reg = tf * c_reg + ti * tg;
                float hl = to * ftanh(c_reg);

                float wv[5]; int ws[5];
                if (i < 5) {
                    // ta needed only while rem<=5 (raw unnormalized scores)
                    float pa = ftanh(hl) * wa_s[tid];
#pragma unroll
                    for (int o = 16; o; o >>= 1) pa += __shfl_xor_sync(0xffffffffu, pa, o);
                    if (lane == 0) redA[wrp] = pa;
                    asm volatile("bar.sync 1, 128;" ::: "memory");
                    float ta = redA[0] + redA[1] + redA[2] + redA[3];
                    int rem = i + 1;
#pragma unroll
                    for (int r = 0; r < 5; r++) {
                        if (r < rem) { wv[r] = ta + sb_arr[r]; ws[r] = rowslot[r]; }
                        else         { wv[r] = 0.0f;           ws[r] = 0; }
                    }
                } else {
                    // ta cancels in the clipped-sparse path
                    float d = top5v[4] + EPSV;
                    float ssum = 0.0f;
#pragma unroll
                    for (int q = 0; q < 5; q++) {
                        float v = fmaxf(top5v[q] - d, 0.0f);
                        wv[q] = v; ws[q] = top5s[q];
                        ssum += v;
                    }
                    float inv = 1.0f / (ssum + EPSV);
#pragma unroll
                    for (int q = 0; q < 5; q++) wv[q] *= inv;
                }
                ac = 0.0f;
#pragma unroll
                for (int q = 0; q < 5; q++) ac = fmaf(wv[q], slots[ws[q]][tid], ac);
                float hf = hl + ac;
                h_sh[tid] = hf;          // end of critical tail (no pbv here anymore)
            }
        } else {
            // ---- warp 16: expect_tx + score sbn from h_sh + top-5 (overlaps GEMV) ----
            if (lane == 0) {
                asm volatile("mbarrier.arrive.expect_tx.shared.b64 _, [%0], %1;"
                             :: "r"(mbl + moff), "r"((u32)(G4 * NC * 4)) : "memory");
            }
            if (i > 0) {
                // sbn(i) = sum_j tanh(h(i-1)[j]) * wb[j], read directly from h_sh
                float s = 0.0f;
#pragma unroll
                for (int q = 0; q < 4; q++) {
                    int j = lane + q * 32;
                    s += ftanh(h_sh[j]) * wb_s[j];
                }
#pragma unroll
                for (int o = 16; o; o >>= 1) s += __shfl_xor_sync(0xffffffffu, s, o);
                if (lane == 0) {
                    float sbn = s;
                    if (i < 5) sb_arr[i] = sbn;
                    if (sbn > top5v[4]) {
                        int evs = top5s[4];
                        int q = 4;
                        while (q > 0 && sbn > top5v[q - 1]) {
                            top5v[q] = top5v[q - 1]; top5r[q] = top5r[q - 1]; top5s[q] = top5s[q - 1];
                            q--;
                        }
                        top5v[q] = sbn; top5r[q] = i; top5s[q] = evs;
                        if (i < 5) rowslot[i] = evs;
                        evslot = evs;
                    } else evslot = -1;
                }
            }
            asm volatile("bar.sync 2, 160;" ::: "memory");
        }
        __syncthreads();  // step boundary: h_sh stable for next step's GEMV + scheduler
    }

    // ---- epilogue (rank 0 only; results replicated in every CTA) ----
    if (rank == 0) {
        if (tid < HH) out_c[b * HH + tid] = ac;
        if (tid == 0) {
            float d = top5v[4] + EPSV;
            float ssum = 0.0f, v[5];
#pragma unroll
            for (int q = 0; q < 5; q++) { v[q] = fmaxf(top5v[q] - d, 0.0f); ssum += v[q]; }
            float inv = 1.0f / (ssum + EPSV);
#pragma unroll
            for (int q = 0; q < 5; q++)
                if (v[q] > 0.0f) out_w[b * TT + top5r[q]] = v[q] * inv;
        }
    }
    asm volatile("barrier.cluster.arrive.aligned;" ::: "memory");
    asm volatile("barrier.cluster.wait.aligned;"   ::: "memory");
}

extern "C" void kernel_launch(void* const* d_in, const int* in_sizes, int n_in,
                              void* d_out, int out_size) {
    const float* x    = (const float*)d_in[0];
    const float* W_ih = (const float*)d_in[1];
    const float* W_hh = (const float*)d_in[2];
    const float* b_ih = (const float*)d_in[3];
    const float* b_hh = (const float*)d_in[4];
    const float* w_t  = (const float*)d_in[5];
    float* out = (float*)d_out;

    gxpack_kernel<<<dim3(BB, TT / 16), 512>>>(x, W_ih, W_hh, b_ih, b_hh);

    cudaLaunchConfig_t cfg = {};
    cfg.gridDim  = dim3(NC * BB, 1, 1);   // 32 clusters x 4 CTAs, one batch row each
    cfg.blockDim = dim3(544, 1, 1);
    cfg.dynamicSmemBytes = 0;
    cfg.stream = 0;
    cudaLaunchAttribute attrs[1];
    attrs[0].id = cudaLaunchAttributeClusterDimension;
    attrs[0].val.clusterDim.x = NC;
    attrs[0].val.clusterDim.y = 1;
    attrs[0].val.clusterDim.z = 1;
    cfg.attrs = attrs;
    cfg.numAttrs = 1;
    cudaLaunchKernelEx(&cfg, rec_kernel, w_t, out);
}

// round 17
// speedup vs baseline: 1.9961x; 1.9961x over previous
#include <cuda_runtime.h>
#include <stdint.h>
#include <math.h>

#define BB 32
#define TT 256
#define INS 64
#define HH 128
#define G4 512
#define EPSV 1e-7f
#define NC 4              // CTAs per cluster (k-split quarters)

typedef unsigned long long u64;
typedef unsigned int u32;

// ---- static device scratch (no cudaMalloc allowed) ----
__device__ __align__(16) u64 g_whp[32 * 512 * 2];   // W_hh packed: [k4][row] -> float4 as 2x u64
__device__ float g_gx[BB * TT * G4];                // precomputed input gate contributions

__device__ __forceinline__ u64 ffma2(u64 a, u64 b, u64 c) {
    u64 d;
    asm("fma.rn.f32x2 %0, %1, %2, %3;" : "=l"(d) : "l"(a), "l"(b), "l"(c));
    return d;
}
__device__ __forceinline__ float f2sum(u64 v) {
    float2 f = *reinterpret_cast<float2*>(&v);
    return f.x + f.y;
}
// accuracy-safe nonlinearities (tanh.approx fails the attn_w check: R10)
__device__ __forceinline__ float fsig(float x)  { return 1.0f / (1.0f + __expf(-x)); }
__device__ __forceinline__ float ftanh(float x) { return 2.0f / (1.0f + __expf(-2.0f * x)) - 1.0f; }

__device__ __forceinline__ u32 smem_u32(const void* p) {
    u32 a;
    asm("{ .reg .u64 t; cvta.to.shared.u64 t, %1; cvt.u32.u64 %0, t; }" : "=r"(a) : "l"(p));
    return a;
}

__device__ __forceinline__ void mbar_wait(u32 mb, u32 parity) {
    asm volatile(
        "{\n\t"
        ".reg .pred P;\n\t"
        "WL_%=:\n\t"
        "mbarrier.try_wait.parity.acquire.cta.shared::cta.b64 P, [%0], %1, 0x989680;\n\t"
        "@P bra.uni WD_%=;\n\t"
        "bra.uni WL_%=;\n\t"
        "WD_%=:\n\t"
        "}"
        :: "r"(mb), "r"(parity) : "memory");
}
__device__ __forceinline__ void st_async_f32(u32 addr, float v, u32 mb) {
    asm volatile("st.async.shared::cluster.mbarrier::complete_tx::bytes.f32 [%0], %1, [%2];"
                 :: "r"(addr), "f"(v), "r"(mb) : "memory");
}

// ---------------- fused pack + gx kernel ----------------
__global__ __launch_bounds__(512) void gxpack_kernel(const float* __restrict__ x,
                                                     const float* __restrict__ W_ih,
                                                     const float* __restrict__ W_hh,
                                                     const float* __restrict__ b_ih,
                                                     const float* __restrict__ b_hh) {
    int b = blockIdx.x, ty = blockIdx.y, j = threadIdx.x;

    if (ty == 0) {
        float* whp = (float*)g_whp;
        for (int idx = b * 512 + j; idx < G4 * HH; idx += 32 * 512) {
            int r = idx >> 7, k = idx & 127;
            whp[((k >> 2) * 512 + r) * 4 + (k & 3)] = W_hh[idx];
        }
    }

    __shared__ float xs[16][INS];
    int t0 = ty * 16;
    for (int idx = j; idx < 16 * INS; idx += 512)
        xs[idx >> 6][idx & 63] = x[(b * TT + t0 + (idx >> 6)) * INS + (idx & 63)];

    float4 w[16];
    const float4* wr = (const float4*)(W_ih + j * INS);
#pragma unroll
    for (int k4 = 0; k4 < 16; k4++) w[k4] = wr[k4];
    float bs = b_ih[j] + b_hh[j];
    __syncthreads();

    for (int tt = 0; tt < 16; tt++) {
        float acc = bs;
#pragma unroll
        for (int k4 = 0; k4 < 16; k4++) {
            acc = fmaf(w[k4].x, xs[tt][4 * k4 + 0], acc);
            acc = fmaf(w[k4].y, xs[tt][4 * k4 + 1], acc);
            acc = fmaf(w[k4].z, xs[tt][4 * k4 + 2], acc);
            acc = fmaf(w[k4].w, xs[tt][4 * k4 + 3], acc);
        }
        g_gx[(b * TT + t0 + tt) * G4 + j] = acc;
    }
}

// ---------------- recurrent kernel: cluster of 4 CTAs per batch row ----------------
// (R15 skeleton: gpart[p][quarter][gate], tid*4 conflict-free st.async)
// CTA rank r handles k-quarter r (32 cols, 16 regs/thread). Partials broadcast
// all-to-all via st.async (4 dsts, tx-counted, expect 8192B). Tail + top-5 fully
// replicated per CTA. Warp 16 = scheduler (expect_tx + sbn from h_sh + top-5).
__global__ __launch_bounds__(544) void rec_kernel(const float* __restrict__ w_t,
                                                  float* __restrict__ out) {
    int tid = threadIdx.x, lane = tid & 31, wrp = tid >> 5;
    int b = blockIdx.x >> 2;

    u32 rank;
    asm("mov.u32 %0, %%cluster_ctarank;" : "=r"(rank));

    __shared__ __align__(16) float h_sh[HH];
    __shared__ float gpart[2][NC][G4];             // [parity][kquarter][gate] (16 KB)
    __shared__ __align__(16) float slots[5][HH];
    __shared__ float redA[4];
    __shared__ float sb_arr[8];
    __shared__ float top5v[5];
    __shared__ int   top5r[5], top5s[5], rowslot[5], evslot;
    __shared__ float wa_s[HH], wb_s[HH];
    __shared__ __align__(8) u64 mbar[2];

    float* out_c = out;             // [B,H]
    float* out_w = out + BB * HH;   // [B,T]
    const float* gxb = g_gx + (size_t)b * TT * G4;

    if (tid < HH) {
        h_sh[tid] = 0.0f;
        slots[0][tid] = 0.0f;
        wa_s[tid] = w_t[tid];
        wb_s[tid] = w_t[HH + tid];
    }
    if (tid == 0) {
        sb_arr[0] = 0.0f;
        top5v[0] = 0.0f; top5r[0] = 0; top5s[0] = 0;
        for (int q = 1; q < 5; q++) { top5v[q] = -1e30f; top5r[q] = -1; top5s[q] = q; }
        rowslot[0] = 0;
        evslot = -1;
        asm volatile("mbarrier.init.shared.b64 [%0], 1;" :: "r"(smem_u32(&mbar[0])) : "memory");
        asm volatile("mbarrier.init.shared.b64 [%0], 1;" :: "r"(smem_u32(&mbar[1])) : "memory");
    }
    if (rank == 0 && tid < TT) out_w[b * TT + tid] = 0.0f;

    // destination addresses in all 4 CTAs: gpart[0][myrank][0] and mbar[0]
    u32 mbl = smem_u32(&mbar[0]);
    u32 gll = smem_u32(&gpart[0][rank][0]);
    u32 dg[NC], dm[NC];
#pragma unroll
    for (int r = 0; r < NC; r++) {
        asm("mapa.shared::cluster.u32 %0, %1, %2;" : "=r"(dg[r]) : "r"(gll), "r"((u32)r));
        asm("mapa.shared::cluster.u32 %0, %1, %2;" : "=r"(dm[r]) : "r"(mbl), "r"((u32)r));
    }

    float c_reg = 0.0f;
    float ac = 0.0f;
    u32 ph0 = 0, ph1 = 0;

    // this CTA's W_hh quarter: rows = gate (tid), cols = [rank*32, rank*32+32)
    ulonglong2 wc[8];
    float gxv = 0.0f;
    if (tid < 512) {
        const ulonglong2* wp = (const ulonglong2*)g_whp;
#pragma unroll
        for (int k4 = 0; k4 < 8; k4++) wc[k4] = wp[((int)rank * 8 + k4) * 512 + tid];
        if (rank == 0) gxv = gxb[tid];   // gx folded into rank-0 partial
    }

    __syncthreads();
    asm volatile("barrier.cluster.arrive.aligned;" ::: "memory");
    asm volatile("barrier.cluster.wait.aligned;"   ::: "memory");

    for (int i = 0; i < TT; i++) {
        int p = i & 1;
        u32 poff = (u32)p * (u32)(NC * G4 * 4);   // parity offset in gpart
        u32 moff = (u32)p * 8u;                   // parity offset in mbar

        if (tid < 512) {
            // ---- GEMV quarter (register weights); rank 0 adds gx ----
            const ulonglong2* h2 = (const ulonglong2*)h_sh;
            u64 a0 = 0ull, a1 = 0ull, a2 = 0ull, a3 = 0ull;
#pragma unroll
            for (int k4 = 0; k4 < 8; k4++) {
                ulonglong2 w = wc[k4];
                ulonglong2 hv = h2[(int)rank * 8 + k4];
                if (k4 & 1) { a2 = ffma2(w.x, hv.x, a2); a3 = ffma2(w.y, hv.y, a3); }
                else        { a0 = ffma2(w.x, hv.x, a0); a1 = ffma2(w.y, hv.y, a1); }
            }
            float part = gxv + (f2sum(a0) + f2sum(a1)) + (f2sum(a2) + f2sum(a3));
            if (rank == 0 && i + 1 < TT) gxv = gxb[(i + 1) * G4 + tid];  // prefetch

            // broadcast partial to all 4 CTAs (conflict-free tid*4 addressing)
            u32 toff = poff + tid * 4u;
#pragma unroll
            for (int r = 0; r < NC; r++)
                st_async_f32(dg[r] + toff, part, dm[r] + moff);

            if (tid < HH) {
                // overlap DSMEM RTT: sync with scheduler warp, insert evicted slot
                asm volatile("bar.sync 2, 160;" ::: "memory");
                int ev = evslot;
                if (ev >= 0) slots[ev][tid] = h_sh[tid];   // row i = h(i-1)

                // wait for all 8192 bytes of partials
                if (p) { mbar_wait(mbl + 8u, ph1); ph1 ^= 1u; }
                else   { mbar_wait(mbl,      ph0); ph0 ^= 1u; }

                // gates = sum of 4 k-quarters
                float gi = gpart[p][0][tid]          + gpart[p][1][tid]
                         + gpart[p][2][tid]          + gpart[p][3][tid];
                float gf = gpart[p][0][HH + tid]     + gpart[p][1][HH + tid]
                         + gpart[p][2][HH + tid]     + gpart[p][3][HH + tid];
                float gg = gpart[p][0][2*HH + tid]   + gpart[p][1][2*HH + tid]
                         + gpart[p][2][2*HH + tid]   + gpart[p][3][2*HH + tid];
                float go = gpart[p][0][3*HH + tid]   + gpart[p][1][3*HH + tid]
                         + gpart[p][2][3*HH + tid]   + gpart[p][3][3*HH + tid];
                float ti = fsig(gi), tf = fsig(gf), tg = ftanh(gg), to = fsig(go);
                c_reg = tf * c_reg + ti * tg;
                float hl = to * ftanh(c_reg);

                float wv[5]; int ws[5];
                if (i < 5) {
                    // ta needed only while rem<=5 (raw unnormalized scores)
                    float pa = ftanh(hl) * wa_s[tid];
#pragma unroll
                    for (int o = 16; o; o >>= 1) pa += __shfl_xor_sync(0xffffffffu, pa, o);
                    if (lane == 0) redA[wrp] = pa;
                    asm volatile("bar.sync 1, 128;" ::: "memory");
                    float ta = redA[0] + redA[1] + redA[2] + redA[3];
                    int rem = i + 1;
#pragma unroll
                    for (int r = 0; r < 5; r++) {
                        if (r < rem) { wv[r] = ta + sb_arr[r]; ws[r] = rowslot[r]; }
                        else         { wv[r] = 0.0f;           ws[r] = 0; }
                    }
                } else {
                    // ta cancels in the clipped-sparse path
                    float d = top5v[4] + EPSV;
                    float ssum = 0.0f;
#pragma unroll
                    for (int q = 0; q < 5; q++) {
                        float v = fmaxf(top5v[q] - d, 0.0f);
                        wv[q] = v; ws[q] = top5s[q];
                        ssum += v;
                    }
                    float inv = 1.0f / (ssum + EPSV);
#pragma unroll
                    for (int q = 0; q < 5; q++) wv[q] *= inv;
                }
                ac = 0.0f;
#pragma unroll
                for (int q = 0; q < 5; q++) ac = fmaf(wv[q], slots[ws[q]][tid], ac);
                float hf = hl + ac;
                h_sh[tid] = hf;          // end of critical tail (pbv moved to scheduler)
            }
        } else {
            // ---- warp 16: expect_tx + sbn from h_sh + top-5 (overlaps GEMV) ----
            if (lane == 0) {
                asm volatile("mbarrier.arrive.expect_tx.shared.b64 _, [%0], %1;"
                             :: "r"(mbl + moff), "r"((u32)(NC * G4 * 4)) : "memory");
            }
            if (i > 0) {
                // sbn(i) = sum_j tanh(h(i-1)[j]) * wb[j], read directly from h_sh
                float s = 0.0f;
#pragma unroll
                for (int q = 0; q < 4; q++) {
                    int j = lane + q * 32;
                    s += ftanh(h_sh[j]) * wb_s[j];
                }
#pragma unroll
                for (int o = 16; o; o >>= 1) s += __shfl_xor_sync(0xffffffffu, s, o);
                if (lane == 0) {
                    float sbn = s;
                    if (i < 5) sb_arr[i] = sbn;
                    if (sbn > top5v[4]) {
                        int evs = top5s[4];
                        int q = 4;
                        while (q > 0 && sbn > top5v[q - 1]) {
                            top5v[q] = top5v[q - 1]; top5r[q] = top5r[q - 1]; top5s[q] = top5s[q - 1];
                            q--;
                        }
                        top5v[q] = sbn; top5r[q] = i; top5s[q] = evs;
                        if (i < 5) rowslot[i] = evs;
                        evslot = evs;
                    } else evslot = -1;
                }
            }
            asm volatile("bar.sync 2, 160;" ::: "memory");
        }
        __syncthreads();  // step boundary: h_sh stable for next step's GEMV + scheduler
    }

    // ---- epilogue (rank 0 only; results replicated in every CTA) ----
    if (rank == 0) {
        if (tid < HH) out_c[b * HH + tid] = ac;
        if (tid == 0) {
            float d = top5v[4] + EPSV;
            float ssum = 0.0f, v[5];
#pragma unroll
            for (int q = 0; q < 5; q++) { v[q] = fmaxf(top5v[q] - d, 0.0f); ssum += v[q]; }
            float inv = 1.0f / (ssum + EPSV);
#pragma unroll
            for (int q = 0; q < 5; q++)
                if (v[q] > 0.0f) out_w[b * TT + top5r[q]] = v[q] * inv;
        }
    }
    asm volatile("barrier.cluster.arrive.aligned;" ::: "memory");
    asm volatile("barrier.cluster.wait.aligned;"   ::: "memory");
}

extern "C" void kernel_launch(void* const* d_in, const int* in_sizes, int n_in,
                              void* d_out, int out_size) {
    const float* x    = (const float*)d_in[0];
    const float* W_ih = (const float*)d_in[1];
    const float* W_hh = (const float*)d_in[2];
    const float* b_ih = (const float*)d_in[3];
    const float* b_hh = (const float*)d_in[4];
    const float* w_t  = (const float*)d_in[5];
    float* out = (float*)d_out;

    gxpack_kernel<<<dim3(BB, TT / 16), 512>>>(x, W_ih, W_hh, b_ih, b_hh);

    cudaLaunchConfig_t cfg = {};
    cfg.gridDim  = dim3(NC * BB, 1, 1);   // 32 clusters x 4 CTAs, one batch row each
    cfg.blockDim = dim3(544, 1, 1);
    cfg.dynamicSmemBytes = 0;
    cfg.stream = 0;
    cudaLaunchAttribute attrs[1];
    attrs[0].id = cudaLaunchAttributeClusterDimension;
    attrs[0].val.clusterDim.x = NC;
    attrs[0].val.clusterDim.y = 1;
    attrs[0].val.clusterDim.z = 1;
    cfg.attrs = attrs;
    cfg.numAttrs = 1;
    cudaLaunchKernelEx(&cfg, rec_kernel, w_t, out);
}